// round 12
// baseline (speedup 1.0000x reference)
#include <cuda_runtime.h>
#include <cuda_bf16.h>
#include <math.h>
#include <stdint.h>

#define BB   64
#define SS   1024
#define SZS  256
#define CC   256
#define NN   64
#define NKD  67
#define EPSV 1e-5f
#define PAD  257

// ------------------------- scratch (device globals) -------------------------
__device__ float g_xn [BB * SS * NN];       // x_n    [b][s][n]  16MB
__device__ float g_zc [BB * SZS * NN];      // z_core [b][s][n]   4MB
__device__ float g_kz [BB * CC * NN];       // kernels (z path)  [b][c][n]
__device__ float g_kxp[2 * BB * CC * NN];   // kernels_x partials [b][c][n]
__device__ __nv_bfloat16 g_kh[BB * CC * NN];  // kernels_x post-LN hi [b][c][n]
__device__ __nv_bfloat16 g_kl[BB * CC * NN];  // kernels_x post-LN lo [b][c][n]
__device__ float g_tem[BB * CC];
__device__ __nv_bfloat16 g_wxh[NN * CC];    // Wx^T split hi [n][c]
__device__ __nv_bfloat16 g_wxl[NN * CC];
__device__ __nv_bfloat16 g_wzh[NN * CC];
__device__ __nv_bfloat16 g_wzl[NN * CC];

// ------------------------- helpers -------------------------
__device__ __forceinline__ uint32_t smem_u32(const void* p) {
    uint32_t a;
    asm("{ .reg .u64 tmp; cvta.to.shared.u64 tmp, %1; cvt.u32.u64 %0, tmp; }"
        : "=r"(a) : "l"(p));
    return a;
}
__device__ __forceinline__ void split_pack(float x0, float x1, uint32_t& h, uint32_t& l) {
    __nv_bfloat162 hp = __floats2bfloat162_rn(x0, x1);
    float r0 = x0 - __bfloat162float(hp.x);
    float r1 = x1 - __bfloat162float(hp.y);
    __nv_bfloat162 lp = __floats2bfloat162_rn(r0, r1);
    h = *reinterpret_cast<uint32_t*>(&hp);
    l = *reinterpret_cast<uint32_t*>(&lp);
}
__device__ __forceinline__ void ldm4(uint32_t addr, uint32_t* r) {
    asm volatile("ldmatrix.sync.aligned.m8n8.x4.shared.b16 {%0,%1,%2,%3}, [%4];"
                 : "=r"(r[0]), "=r"(r[1]), "=r"(r[2]), "=r"(r[3]) : "r"(addr));
}
__device__ __forceinline__ void mma16816(float* d, const uint32_t* a, const uint32_t* b) {
    asm volatile(
        "mma.sync.aligned.m16n8k16.row.col.f32.bf16.bf16.f32 "
        "{%0,%1,%2,%3}, {%4,%5,%6,%7}, {%8,%9}, {%0,%1,%2,%3};"
        : "+f"(d[0]), "+f"(d[1]), "+f"(d[2]), "+f"(d[3])
        : "r"(a[0]), "r"(a[1]), "r"(a[2]), "r"(a[3]), "r"(b[0]), "r"(b[1]));
}
__device__ __forceinline__ void cp16(uint32_t dst, const void* src) {
    asm volatile("cp.async.cg.shared.global [%0], [%1], 16;" :: "r"(dst), "l"(src));
}
__device__ __forceinline__ void cpcommit() {
    asm volatile("cp.async.commit_group;" ::: "memory");
}
template<int N> __device__ __forceinline__ void cpwait() {
    asm volatile("cp.async.wait_group %0;" :: "n"(N) : "memory");
}

// bf16 smem row stride (bytes): 72 halves = 144B
#define RS 144
// raw staging strides (floats)
#define RAWA_F  68    // non-TRA: 128 rows x 64+pad
#define RAWAT_F 132   // TRA: 64 k-rows x 128+pad
#define RAWB_F  68    // 64 rows x 64+pad
// kOuter smem layout (bytes) — single-buffered raw, 2 CTAs/SM
#define OFF_AH   0        // 128*144 = 18432
#define OFF_AL   18432
#define OFF_BH   36864    // 64*144 = 9216
#define OFF_BL   46080
#define OFF_RAWA 55296    // 34816
#define OFF_RAWB 90112    // 17408
#define OFF_BIAS 107520   // 256
#define SMEM_KG  107776
// kLin v2 smem layout (no raw staging)
#define LN_AH   0         // 18432
#define LN_AL   18432
#define LN_BH   36864     // 9216
#define LN_BL   46080
#define LN_BIAS 55296
#define SMEM_LN 55552

// ---------------------------------------------------------------------------
// kPrep: split Wx/Wz (fp32 [c][n]) into bf16 hi/lo transposed [n][c]
// ---------------------------------------------------------------------------
__global__ void kPrep(const float* __restrict__ Wx, const float* __restrict__ Wz) {
    int idx = blockIdx.x * 256 + threadIdx.x;
    for (; idx < CC * NN; idx += gridDim.x * 256) {
        int c = idx >> 6, n = idx & 63;
        float vx = Wx[idx];
        __nv_bfloat16 hx = __float2bfloat16(vx);
        g_wxh[n * CC + c] = hx;
        g_wxl[n * CC + c] = __float2bfloat16(vx - __bfloat162float(hx));
        float vz = Wz[idx];
        __nv_bfloat16 hz = __float2bfloat16(vz);
        g_wzh[n * CC + c] = hz;
        g_wzl[n * CC + c] = __float2bfloat16(vz - __bfloat162float(hz));
    }
}

// ---------------------------------------------------------------------------
// lin_tile: D[m0..m0+127, 0..63] = A[m,:] @ W^T[:,n] + bias, K=256 (4 chunks).
// A: fp32 [m][k], register-convert. B: pre-split bf16 [n][k], pure cp.async.
// 256 threads = 8 warps (4M x 2N), 2 CTAs/SM.
// ---------------------------------------------------------------------------
__device__ void lin_tile(const float* __restrict__ Ab,
                         const __nv_bfloat16* __restrict__ wh,
                         const __nv_bfloat16* __restrict__ wl,
                         float* __restrict__ Db,
                         int m0, const float* __restrict__ bias, char* sm) {
    uint32_t sb = smem_u32(sm);
    int t = threadIdx.x, warp = t >> 5, l = t & 31;
    int wm = (warp & 3) * 32;
    int wn = (warp >> 2) * 32;
    float* sBias = (float*)(sm + LN_BIAS);
    if (t < 64) sBias[t] = bias[t];

    float acc[2][4][4];
#pragma unroll
    for (int i = 0; i < 2; i++)
#pragma unroll
        for (int j = 0; j < 4; j++)
#pragma unroll
            for (int q = 0; q < 4; q++) acc[i][j][q] = 0.f;

    uint32_t aRow = wm + (l & 15);
    uint32_t aOff = ((l >> 4) & 1) * 16;
    uint32_t aHi = sb + LN_AH + aRow * RS + aOff;
    uint32_t aLo = sb + LN_AL + aRow * RS + aOff;
    uint32_t bRow = wn + (l & 7) + ((l & 16) ? 8 : 0);
    uint32_t bOff = (l & 8) ? 16 : 0;
    uint32_t bHi = sb + LN_BH + bRow * RS + bOff;
    uint32_t bLo = sb + LN_BL + bRow * RS + bOff;

#pragma unroll 1
    for (int ch = 0; ch < 4; ch++) {
        int k0 = ch << 6;
        // B: pure cp.async copy of pre-split weights (64 rows x 8 x 16B, hi+lo)
#pragma unroll
        for (int i = 0; i < 2; i++) {
            int u = t + i * 256;
            int r = u >> 3, kq = u & 7;
            cp16(sb + LN_BH + r * RS + kq * 16, wh + r * CC + k0 + kq * 8);
        }
#pragma unroll
        for (int i = 0; i < 2; i++) {
            int u = t + i * 256;
            int r = u >> 3, kq = u & 7;
            cp16(sb + LN_BL + r * RS + kq * 16, wl + r * CC + k0 + kq * 8);
        }
        cpcommit();
        // A: LDG fp32 -> register split -> smem (128 rows x 16 kq)
        {
            char* sAh = sm + LN_AH;
            char* sAl = sm + LN_AL;
#pragma unroll
            for (int i = 0; i < 8; i++) {
                int u = t + i * 256;
                int r = u >> 4, kq = u & 15;
                float4 v = *(const float4*)(Ab + (size_t)(m0 + r) * CC + k0 + kq * 4);
                uint32_t h0, l0, h1, l1;
                split_pack(v.x, v.y, h0, l0);
                split_pack(v.z, v.w, h1, l1);
                *(uint2*)(sAh + r * RS + kq * 8) = make_uint2(h0, h1);
                *(uint2*)(sAl + r * RS + kq * 8) = make_uint2(l0, l1);
            }
        }
        cpwait<0>();
        __syncthreads();
#pragma unroll
        for (int ks = 0; ks < 4; ks++) {
            uint32_t ah[2][4], al[2][4], bh[2][4], bl[2][4];
#pragma unroll
            for (int mf = 0; mf < 2; mf++) {
                ldm4(aHi + mf * (16 * RS) + ks * 32, ah[mf]);
                ldm4(aLo + mf * (16 * RS) + ks * 32, al[mf]);
            }
#pragma unroll
            for (int p = 0; p < 2; p++) {
                ldm4(bHi + p * (16 * RS) + ks * 32, bh[p]);
                ldm4(bLo + p * (16 * RS) + ks * 32, bl[p]);
            }
#pragma unroll
            for (int mf = 0; mf < 2; mf++)
#pragma unroll
                for (int nf = 0; nf < 4; nf++) {
                    const uint32_t* bhp = &bh[nf >> 1][(nf & 1) * 2];
                    const uint32_t* blp = &bl[nf >> 1][(nf & 1) * 2];
                    mma16816(acc[mf][nf], ah[mf], bhp);
                    mma16816(acc[mf][nf], ah[mf], blp);
                    mma16816(acc[mf][nf], al[mf], bhp);
                }
        }
        __syncthreads();
    }

#pragma unroll
    for (int mf = 0; mf < 2; mf++)
#pragma unroll
        for (int nf = 0; nf < 4; nf++) {
            int row = m0 + wm + mf * 16 + (l >> 2);
            int col = wn + nf * 8 + (l & 3) * 2;
            float b0 = sBias[col];
            float b1 = sBias[col + 1];
            *(float2*)(Db + (size_t)row * NN + col) =
                make_float2(acc[mf][nf][0] + b0, acc[mf][nf][1] + b1);
            *(float2*)(Db + (size_t)(row + 8) * NN + col) =
                make_float2(acc[mf][nf][2] + b0, acc[mf][nf][3] + b1);
        }
}

// ---------------------------------------------------------------------------
// merged launch 1: x_n = X@Wx+bx (512 tiles) and z_core = Z@Wz+bz (128 tiles)
// ---------------------------------------------------------------------------
__global__ void __launch_bounds__(256, 2) kLinAll(
    const float* __restrict__ xf, const float* __restrict__ bx,
    const float* __restrict__ zf, const float* __restrict__ bz,
    float* __restrict__ xn, float* __restrict__ zcp) {
    extern __shared__ char sm[];
    int bid = blockIdx.x;
    if (bid < 512) {
        int b = bid >> 3, m0 = (bid & 7) * 128;
        lin_tile(xf + (size_t)b * SS * CC, g_wxh, g_wxl,
                 xn + (size_t)b * SS * NN, m0, bx, sm);
    } else {
        int zi = bid - 512;
        int b = zi >> 1, m0 = (zi & 1) * 128;
        lin_tile(zf + (size_t)b * SZS * CC, g_wzh, g_wzl,
                 zcp + (size_t)b * SZS * NN, m0, bz, sm);
    }
}

// ---------------------------------------------------------------------------
// kOuter machinery (unchanged, measured-good): raw cp.async staging + convert
// ---------------------------------------------------------------------------
__device__ __forceinline__ void ko_load(const float* Ab, int lda, const float* Bb,
                                        int ldb, int m0, int k0, char* sm, int t) {
    uint32_t ra = smem_u32(sm + OFF_RAWA);
    uint32_t rb = smem_u32(sm + OFF_RAWB);
#pragma unroll
    for (int i = 0; i < 8; i++) {
        int u = t + i * 256;
        int r = u >> 5, mq = u & 31;
        cp16(ra + r * (RAWAT_F * 4) + mq * 16,
             Ab + (size_t)(k0 + r) * lda + m0 + mq * 4);
    }
#pragma unroll
    for (int i = 0; i < 4; i++) {
        int u = t + i * 256;
        int r = u >> 4, nq = u & 15;
        cp16(rb + r * (RAWB_F * 4) + nq * 16,
             Bb + (size_t)(k0 + r) * ldb + nq * 4);
    }
}
__device__ __forceinline__ void ko_convert(char* sm, int t) {
    float* rawA = (float*)(sm + OFF_RAWA);
    float* rawB = (float*)(sm + OFF_RAWB);
    char* sAh = sm + OFF_AH; char* sAl = sm + OFF_AL;
    char* sBh = sm + OFF_BH; char* sBl = sm + OFF_BL;
#pragma unroll
    for (int i = 0; i < 8; i++) {
        int u = t + i * 256;
        int m = u & 127, kg = u >> 7;
        float f0 = rawA[(kg * 4 + 0) * RAWAT_F + m];
        float f1 = rawA[(kg * 4 + 1) * RAWAT_F + m];
        float f2 = rawA[(kg * 4 + 2) * RAWAT_F + m];
        float f3 = rawA[(kg * 4 + 3) * RAWAT_F + m];
        uint32_t h0, l0, h1, l1;
        split_pack(f0, f1, h0, l0);
        split_pack(f2, f3, h1, l1);
        *(uint2*)(sAh + m * RS + kg * 8) = make_uint2(h0, h1);
        *(uint2*)(sAl + m * RS + kg * 8) = make_uint2(l0, l1);
    }
#pragma unroll
    for (int i = 0; i < 4; i++) {
        int u = t + i * 256;
        int n = u & 63, kg = u >> 6;
        float f0 = rawB[(kg * 4 + 0) * RAWB_F + n];
        float f1 = rawB[(kg * 4 + 1) * RAWB_F + n];
        float f2 = rawB[(kg * 4 + 2) * RAWB_F + n];
        float f3 = rawB[(kg * 4 + 3) * RAWB_F + n];
        uint32_t h0, l0, h1, l1;
        split_pack(f0, f1, h0, l0);
        split_pack(f2, f3, h1, l1);
        *(uint2*)(sBh + n * RS + kg * 8) = make_uint2(h0, h1);
        *(uint2*)(sBl + n * RS + kg * 8) = make_uint2(l0, l1);
    }
}

__device__ void outer_tile(const float* __restrict__ Ab, int lda,
                           const float* __restrict__ Bb, int ldb,
                           float* __restrict__ Db, int ldd,
                           int m0, int Ktot, char* sm) {
    uint32_t sb = smem_u32(sm);
    int t = threadIdx.x, warp = t >> 5, l = t & 31;
    int wm = (warp & 3) * 32;
    int wn = (warp >> 2) * 32;

    float acc[2][4][4];
#pragma unroll
    for (int i = 0; i < 2; i++)
#pragma unroll
        for (int j = 0; j < 4; j++)
#pragma unroll
            for (int q = 0; q < 4; q++) acc[i][j][q] = 0.f;

    uint32_t aRow = wm + (l & 15);
    uint32_t aOff = ((l >> 4) & 1) * 16;
    uint32_t aHi = sb + OFF_AH + aRow * RS + aOff;
    uint32_t aLo = sb + OFF_AL + aRow * RS + aOff;
    uint32_t bRow = wn + (l & 7) + ((l & 16) ? 8 : 0);
    uint32_t bOff = (l & 8) ? 16 : 0;
    uint32_t bHi = sb + OFF_BH + bRow * RS + bOff;
    uint32_t bLo = sb + OFF_BL + bRow * RS + bOff;

    int nch = Ktot >> 6;
    for (int ch = 0; ch < nch; ch++) {
        ko_load(Ab, lda, Bb, ldb, m0, ch << 6, sm, t);
        cpcommit();
        cpwait<0>();
        __syncthreads();
        ko_convert(sm, t);
        __syncthreads();
#pragma unroll
        for (int ks = 0; ks < 4; ks++) {
            uint32_t ah[2][4], al[2][4], bh[2][4], bl[2][4];
#pragma unroll
            for (int mf = 0; mf < 2; mf++) {
                ldm4(aHi + mf * (16 * RS) + ks * 32, ah[mf]);
                ldm4(aLo + mf * (16 * RS) + ks * 32, al[mf]);
            }
#pragma unroll
            for (int p = 0; p < 2; p++) {
                ldm4(bHi + p * (16 * RS) + ks * 32, bh[p]);
                ldm4(bLo + p * (16 * RS) + ks * 32, bl[p]);
            }
#pragma unroll
            for (int mf = 0; mf < 2; mf++)
#pragma unroll
                for (int nf = 0; nf < 4; nf++) {
                    const uint32_t* bhp = &bh[nf >> 1][(nf & 1) * 2];
                    const uint32_t* blp = &bl[nf >> 1][(nf & 1) * 2];
                    mma16816(acc[mf][nf], ah[mf], bhp);
                    mma16816(acc[mf][nf], ah[mf], blp);
                    mma16816(acc[mf][nf], al[mf], bhp);
                }
        }
        __syncthreads();
    }

#pragma unroll
    for (int mf = 0; mf < 2; mf++)
#pragma unroll
        for (int nf = 0; nf < 4; nf++) {
            int row = m0 + wm + mf * 16 + (l >> 2);
            int col = wn + nf * 8 + (l & 3) * 2;
            *(float2*)(Db + (size_t)row * ldd + col) =
                make_float2(acc[mf][nf][0], acc[mf][nf][1]);
            *(float2*)(Db + (size_t)(row + 8) * ldd + col) =
                make_float2(acc[mf][nf][2], acc[mf][nf][3]);
        }
}

// ---------------------------------------------------------------------------
// merged launch 2: kx partials (s-split x2, 256 tiles) and kz (128 tiles)
// ---------------------------------------------------------------------------
__global__ void __launch_bounds__(256, 2) kOuterAll(
    const float* __restrict__ xf, const float* __restrict__ zf,
    const float* __restrict__ xn, const float* __restrict__ zcp,
    float* __restrict__ kxp, float* __restrict__ kz) {
    extern __shared__ char sm[];
    int bid = blockIdx.x;
    if (bid < 256) {
        int b = bid >> 2, q = bid & 3, tile = q & 1, half = q >> 1;
        outer_tile(
            xf + (size_t)b * SS * CC + (size_t)half * 512 * CC, CC,
            xn + (size_t)b * SS * NN + (size_t)half * 512 * NN, NN,
            kxp + (size_t)half * BB * CC * NN + (size_t)b * CC * NN, NN,
            tile * 128, 512, sm);
    } else {
        int zi = bid - 256;
        int b = zi >> 1, tile = zi & 1;
        outer_tile(
            zf + (size_t)b * SZS * CC, CC, zcp + (size_t)b * SZS * NN, NN,
            kz + (size_t)b * CC * NN, NN, tile * 128, SZS, sm);
    }
}

// ---------------------------------------------------------------------------
// kD: dysep conv atten + layernorm + proto + tem. grid(64), 512 threads.
// Writes split-bf16 kernels (g_kh/g_kl, [b][c][n]) and g_tem.
// ---------------------------------------------------------------------------
__global__ void kD(const float* __restrict__ Wdyn, const float* __restrict__ bdyn,
                   const float* __restrict__ gn, const float* __restrict__ bn,
                   const float* __restrict__ Wp, const float* __restrict__ bp) {
    extern __shared__ float smf[];
    float* sKz = smf;            // 64 x PAD (reused later as sP)
    float* sV  = smf + 16448;    // 64 x PAD
    float* sU  = smf + 32896;    // WdynT staging (68-stride), then depth 64x256
    float* sDy = smf + 50304;    // 64 x 68
    float* sPr = smf + 54656;    // 64
    int b = blockIdx.x, t = threadIdx.x;

    const float* kzb = g_kz + (size_t)b * CC * NN;
    const float* kx0 = g_kxp + (size_t)b * CC * NN;
    const float* kx1 = g_kxp + (size_t)BB * CC * NN + (size_t)b * CC * NN;
    for (int idx = t; idx < CC * NN; idx += 512) {
        int c = idx >> 6, n = idx & 63;
        sKz[n * PAD + c] = kzb[idx];
        sV [n * PAD + c] = kx0[idx] + kx1[idx];
    }
    for (int idx = t; idx < CC * NKD; idx += 512) {
        int c = idx / NKD, jj = idx - c * NKD;
        sU[c * 68 + jj] = Wdyn[idx];
    }
    __syncthreads();

    // dy[m,jj] = kz[m,:] . Wdyn[:,jj] + bdyn[jj]
#pragma unroll
    for (int k = 0; k < 9; k++) {
        int o = t + k * 512;
        if (o < NN * NKD) {
            int m = o / NKD, jj = o - m * NKD;
            const float* kzr = sKz + m * PAD;
            const float* wc  = sU + jj;
            float a0 = 0.f, a1 = 0.f, a2 = 0.f, a3 = 0.f;
            for (int c = 0; c < CC; c += 4) {
                a0 += kzr[c + 0] * wc[(c + 0) * 68];
                a1 += kzr[c + 1] * wc[(c + 1) * 68];
                a2 += kzr[c + 2] * wc[(c + 2) * 68];
                a3 += kzr[c + 3] * wc[(c + 3) * 68];
            }
            sDy[m * 68 + jj] = bdyn[jj] + ((a0 + a1) + (a2 + a3));
        }
    }
    __syncthreads();

    // depth(m,c) = relu(w0*v[c-1] + w1*v[c] + w2*v[c+1])  (overwrites sU)
    for (int idx = t; idx < NN * CC; idx += 512) {
        int m = idx >> 8, c = idx & 255;
        float w0 = sDy[m * 68 + 0], w1 = sDy[m * 68 + 1], w2 = sDy[m * 68 + 2];
        float vm = (c > 0)   ? sV[m * PAD + c - 1] : 0.f;
        float v0 = sV[m * PAD + c];
        float vp = (c < 255) ? sV[m * PAD + c + 1] : 0.f;
        float d = w0 * vm + w1 * v0 + w2 * vp;
        sU[idx] = d > 0.f ? d : 0.f;
    }
    __syncthreads();

    // point(n,c) = sum_m wp[n,m]*depth[m,c]; layernorm over c
    int tx = t & 31, ty = t >> 5;
    float4 acc[4][2];
#pragma unroll
    for (int i = 0; i < 4; i++) {
        acc[i][0] = make_float4(0.f, 0.f, 0.f, 0.f);
        acc[i][1] = make_float4(0.f, 0.f, 0.f, 0.f);
    }
#pragma unroll 2
    for (int m = 0; m < NN; m++) {
        float4 d0 = *(const float4*)(sU + m * CC + tx * 4);
        float4 d1 = *(const float4*)(sU + m * CC + tx * 4 + 128);
#pragma unroll
        for (int i = 0; i < 4; i++) {
            float w = sDy[(ty * 4 + i) * 68 + 3 + m];
            acc[i][0].x += w * d0.x; acc[i][0].y += w * d0.y;
            acc[i][0].z += w * d0.z; acc[i][0].w += w * d0.w;
            acc[i][1].x += w * d1.x; acc[i][1].y += w * d1.y;
            acc[i][1].z += w * d1.z; acc[i][1].w += w * d1.w;
        }
    }
    __syncthreads();

    float* sP = sKz;
    float4 gg0 = *(const float4*)(gn + tx * 4);
    float4 gg1 = *(const float4*)(gn + tx * 4 + 128);
    float4 bb0 = *(const float4*)(bn + tx * 4);
    float4 bb1 = *(const float4*)(bn + tx * 4 + 128);
#pragma unroll
    for (int i = 0; i < 4; i++) {
        int n = ty * 4 + i;
        float4 v0 = acc[i][0], v1 = acc[i][1];
        float sum = v0.x + v0.y + v0.z + v0.w + v1.x + v1.y + v1.z + v1.w;
        float sq  = v0.x * v0.x + v0.y * v0.y + v0.z * v0.z + v0.w * v0.w
                  + v1.x * v1.x + v1.y * v1.y + v1.z * v1.z + v1.w * v1.w;
#pragma unroll
        for (int off = 16; off >= 1; off >>= 1) {
            sum += __shfl_xor_sync(0xffffffffu, sum, off);
            sq  += __shfl_xor_sync(0xffffffffu, sq, off);
        }
        float mu = sum * (1.f / 256.f);
        float var = sq * (1.f / 256.f) - mu * mu;
        float rs = rsqrtf(var + EPSV);
        float4 o0, o1;
        o0.x = (v0.x - mu) * rs * gg0.x + bb0.x;
        o0.y = (v0.y - mu) * rs * gg0.y + bb0.y;
        o0.z = (v0.z - mu) * rs * gg0.z + bb0.z;
        o0.w = (v0.w - mu) * rs * gg0.w + bb0.w;
        o1.x = (v1.x - mu) * rs * gg1.x + bb1.x;
        o1.y = (v1.y - mu) * rs * gg1.y + bb1.y;
        o1.z = (v1.z - mu) * rs * gg1.z + bb1.z;
        o1.w = (v1.w - mu) * rs * gg1.w + bb1.w;
        *(float4*)(sP + n * CC + tx * 4) = o0;
        *(float4*)(sP + n * CC + tx * 4 + 128) = o1;
    }
    __syncthreads();

    // write split-bf16 kernels [c][n]
    __nv_bfloat16* kh = g_kh + (size_t)b * CC * NN;
    __nv_bfloat16* kl = g_kl + (size_t)b * CC * NN;
    for (int idx = t; idx < NN * CC; idx += 512) {
        int c = idx >> 6, n = idx & 63;
        float v = sP[n * CC + c];
        __nv_bfloat16 h = __float2bfloat16(v);
        float lo = v - __bfloat162float(h);
        kh[idx] = h;
        kl[idx] = __float2bfloat16(lo);
    }

    // proto[n] = ka[n,:] . Wp + bp
    if (t < NN) {
        float a0 = 0.f, a1 = 0.f, a2 = 0.f, a3 = 0.f;
        for (int c = 0; c < CC; c += 4) {
            float4 p = *(const float4*)(sP + t * CC + c);
            float4 w = *(const float4*)(Wp + c);
            a0 += p.x * w.x; a1 += p.y * w.y; a2 += p.z * w.z; a3 += p.w * w.w;
        }
        sPr[t] = bp[0] + ((a0 + a1) + (a2 + a3));
    }
    __syncthreads();

    // tem[c] = sigmoid(sum_n proto[n] * ka[n,c])
    if (t < CC) {
        float a0 = 0.f, a1 = 0.f, a2 = 0.f, a3 = 0.f;
        for (int n = 0; n < NN; n += 4) {
            a0 += sPr[n + 0] * sP[(n + 0) * CC + t];
            a1 += sPr[n + 1] * sP[(n + 1) * CC + t];
            a2 += sPr[n + 2] * sP[(n + 2) * CC + t];
            a3 += sPr[n + 3] * sP[(n + 3) * CC + t];
        }
        float s = (a0 + a1) + (a2 + a3);
        g_tem[b * CC + t] = 1.f / (1.f + expf(-s));
    }
}

// ---------------------------------------------------------------------------
// kXC v4 (unchanged, measured-good): B-persistent, grid(4,64), 2 CTAs/SM.
// ---------------------------------------------------------------------------
#define XC_AH   0
#define XC_AL   9216
#define XC_BH   18432
#define XC_BL   55296
#define XC_TEM  92160
#define XC_G    93184
#define XC_B2   94208
#define XC_SUM  95232
#define XC_SQ   96256
#define SMEM_XC 97280

__global__ void __launch_bounds__(256, 2) kXC(
    const float* __restrict__ xn, const __nv_bfloat16* __restrict__ kh,
    const __nv_bfloat16* __restrict__ kl, const float* __restrict__ xf,
    const float* __restrict__ gl, const float* __restrict__ bl,
    float* __restrict__ out)
{
    extern __shared__ char sm[];
    uint32_t sb = smem_u32(sm);
    float* sTem = (float*)(sm + XC_TEM);
    float* sG   = (float*)(sm + XC_G);
    float* sB2  = (float*)(sm + XC_B2);
    float* sSum = (float*)(sm + XC_SUM);   // [64][4]
    float* sSq  = (float*)(sm + XC_SQ);    // [64][4]

    int t = threadIdx.x, warp = t >> 5, l = t & 31;
    int b = blockIdx.y;
    int sbase = blockIdx.x * 256;
    int wm = (warp & 1) * 32;
    int wn = (warp >> 1) * 64;

    const __nv_bfloat16* Bh = kh + (size_t)b * CC * NN;
    const __nv_bfloat16* Bl = kl + (size_t)b * CC * NN;

#pragma unroll
    for (int i = 0; i < 8; i++) {
        int u = t + i * 256;
        int r = u >> 3, kq = u & 7;
        cp16(sb + XC_BH + r * RS + kq * 16, Bh + r * NN + kq * 8);
    }
#pragma unroll
    for (int i = 0; i < 8; i++) {
        int u = t + i * 256;
        int r = u >> 3, kq = u & 7;
        cp16(sb + XC_BL + r * RS + kq * 16, Bl + r * NN + kq * 8);
    }
    cpcommit();
    { sTem[t] = g_tem[b * CC + t]; sG[t] = gl[t]; sB2[t] = bl[t]; }
    cpwait<0>();
    __syncthreads();

    uint32_t aRow = wm + (l & 15);
    uint32_t aOff = ((l >> 4) & 1) * 16;
    uint32_t aHi = sb + XC_AH + aRow * RS + aOff;
    uint32_t aLo = sb + XC_AL + aRow * RS + aOff;
    uint32_t bRow = wn + (l & 7) + ((l & 16) ? 8 : 0);
    uint32_t bOff = (l & 8) ? 16 : 0;
    uint32_t bHi = sb + XC_BH + bRow * RS + bOff;
    uint32_t bLo = sb + XC_BL + bRow * RS + bOff;

    for (int it = 0; it < 4; it++) {
        int s0 = sbase + it * 64;
        const float* Ab = xn + ((size_t)b * SS + s0) * NN;

        if (it > 0) __syncthreads();

        {
            char* sAh = sm + XC_AH;
            char* sAl = sm + XC_AL;
            for (int idx = t; idx < 1024; idx += 256) {
                int r = idx >> 4, kq = idx & 15;
                float4 v = *(const float4*)(Ab + (size_t)r * NN + kq * 4);
                uint32_t h0, l0, h1, l1;
                split_pack(v.x, v.y, h0, l0);
                split_pack(v.z, v.w, h1, l1);
                *(uint2*)(sAh + r * RS + kq * 8) = make_uint2(h0, h1);
                *(uint2*)(sAl + r * RS + kq * 8) = make_uint2(l0, l1);
            }
        }
        __syncthreads();

        float acc[2][8][4];
#pragma unroll
        for (int i = 0; i < 2; i++)
#pragma unroll
            for (int j = 0; j < 8; j++)
#pragma unroll
                for (int q = 0; q < 4; q++) acc[i][j][q] = 0.f;

#pragma unroll
        for (int ks = 0; ks < 4; ks++) {
            uint32_t ah[2][4], al[2][4], bh[4][4], blr[4][4];
#pragma unroll
            for (int mf = 0; mf < 2; mf++) {
                ldm4(aHi + mf * (16 * RS) + ks * 32, ah[mf]);
                ldm4(aLo + mf * (16 * RS) + ks * 32, al[mf]);
            }
#pragma unroll
            for (int p = 0; p < 4; p++) {
                ldm4(bHi + p * (16 * RS) + ks * 32, bh[p]);
                ldm4(bLo + p * (16 * RS) + ks * 32, blr[p]);
            }
#pragma unroll
            for (int mf = 0; mf < 2; mf++)
#pragma unroll
                for (int nf = 0; nf < 8; nf++) {
                    const uint32_t* bhp = &bh[nf >> 1][(nf & 1) * 2];
                    const uint32_t* blp = &blr[nf >> 1][(nf & 1) * 2];
                    mma16816(acc[mf][nf], ah[mf], bhp);
                    mma16816(acc[mf][nf], ah[mf], blp);
                    mma16816(acc[mf][nf], al[mf], bhp);
                }
        }

        float psum[2][2], psq[2][2];
#pragma unroll
        for (int mf = 0; mf < 2; mf++)
#pragma unroll
            for (int h = 0; h < 2; h++) { psum[mf][h] = 0.f; psq[mf][h] = 0.f; }
#pragma unroll
        for (int nf = 0; nf < 8; nf++) {
            int col = wn + nf * 8 + (l & 3) * 2;
            float t0 = sTem[col], t1 = sTem[col + 1];
#pragma unroll
            for (int mf = 0; mf < 2; mf++) {
                acc[mf][nf][0] *= t0; acc[mf][nf][1] *= t1;
                acc[mf][nf][2] *= t0; acc[mf][nf][3] *= t1;
                psum[mf][0] += acc[mf][nf][0] + acc[mf][nf][1];
                psq [mf][0] += acc[mf][nf][0] * acc[mf][nf][0] + acc[mf][nf][1] * acc[mf][nf][1];
                psum[mf][1] += acc[mf][nf][2] + acc[mf][nf][3];
                psq [mf][1] += acc[mf][nf][2] * acc[mf][nf][2] + acc[mf][nf][3] * acc[mf][nf][3];
            }
        }
#pragma unroll
        for (int mf = 0; mf < 2; mf++)
#pragma unroll
            for (int h = 0; h < 2; h++) {
#pragma unroll
                for (int off = 1; off <= 2; off <<= 1) {
                    psum[mf][h] += __shfl_xor_sync(0xffffffffu, psum[mf][h], off);
                    psq [mf][h] += __shfl_xor_sync(0xffffffffu, psq [mf][h], off);
                }
                if ((l & 3) == 0) {
                    int r = wm + mf * 16 + h * 8 + (l >> 2);
                    sSum[r * 4 + (warp >> 1)] = psum[mf][h];
                    sSq [r * 4 + (warp >> 1)] = psq [mf][h];
                }
            }
        __syncthreads();

        const float* Xb = xf + ((size_t)b * SS + s0) * CC;
        float* Ob = out + ((size_t)b * SS + s0) * CC;
#pragma unroll
        for (int mf = 0; mf < 2; mf++)
#pragma unroll
            for (int h = 0; h < 2; h++) {
                int r = wm + mf * 16 + h * 8 + (l >> 2);
                float sum = sSum[r * 4] + sSum[r * 4 + 1] + sSum[r * 4 + 2] + sSum[r * 4 + 3];
                float sq  = sSq [r * 4] + sSq [r * 4 + 1] + sSq [r * 4 + 2] + sSq [r * 4 + 3];
                float mu = sum * (1.f / 256.f);
                float var = sq * (1.f / 256.f) - mu * mu;
                float rs = rsqrtf(var + EPSV);
#pragma unroll
                for (int nf = 0; nf < 8; nf++) {
                    int col = wn + nf * 8 + (l & 3) * 2;
                    float v0 = acc[mf][nf][h * 2], v1 = acc[mf][nf][h * 2 + 1];
                    float2 xv = *(const float2*)(Xb + (size_t)r * CC + col);
                    float o0 = fmaxf((v0 - mu) * rs * sG[col] + sB2[col], 0.f) + xv.x;
                    float o1 = fmaxf((v1 - mu) * rs * sG[col + 1] + sB2[col + 1], 0.f) + xv.y;
                    *(float2*)(Ob + (size_t)r * CC + col) = make_float2(o0, o1);
                }
            }
    }
}

// ---------------------------------------------------------------------------
extern "C" void kernel_launch(void* const* d_in, const int* in_sizes, int n_in,
                              void* d_out, int out_size) {
    const float* x_feat = (const float*)d_in[0];
    const float* z_feat = (const float*)d_in[1];
    const float* Wz     = (const float*)d_in[2];
    const float* bz     = (const float*)d_in[3];
    const float* Wx     = (const float*)d_in[4];
    const float* bx     = (const float*)d_in[5];
    const float* Wdyn   = (const float*)d_in[6];
    const float* bdyn   = (const float*)d_in[7];
    const float* gnorm  = (const float*)d_in[8];
    const float* bnorm  = (const float*)d_in[9];
    const float* Wp     = (const float*)d_in[10];
    const float* bp     = (const float*)d_in[11];
    const float* g_ln   = (const float*)d_in[12];
    const float* b_ln   = (const float*)d_in[13];
    float* out = (float*)d_out;

    float *xn, *zc, *kz, *kxp;
    __nv_bfloat16 *kh, *kl;
    cudaGetSymbolAddress((void**)&xn,  g_xn);
    cudaGetSymbolAddress((void**)&zc,  g_zc);
    cudaGetSymbolAddress((void**)&kz,  g_kz);
    cudaGetSymbolAddress((void**)&kxp, g_kxp);
    cudaGetSymbolAddress((void**)&kh,  g_kh);
    cudaGetSymbolAddress((void**)&kl,  g_kl);

    cudaFuncSetAttribute(kLinAll,   cudaFuncAttributeMaxDynamicSharedMemorySize, SMEM_LN);
    cudaFuncSetAttribute(kOuterAll, cudaFuncAttributeMaxDynamicSharedMemorySize, SMEM_KG);
    cudaFuncSetAttribute(kD,  cudaFuncAttributeMaxDynamicSharedMemorySize, 218880);
    cudaFuncSetAttribute(kXC, cudaFuncAttributeMaxDynamicSharedMemorySize, SMEM_XC);

    kPrep<<<16, 256>>>(Wx, Wz);
    kLinAll<<<640, 256, SMEM_LN>>>(x_feat, bx, z_feat, bz, xn, zc);
    kOuterAll<<<384, 256, SMEM_KG>>>(x_feat, z_feat, xn, zc, kxp, kz);
    kD<<<BB, 512, 218880>>>(Wdyn, bdyn, gnorm, bnorm, Wp, bp);
    kXC<<<dim3(4, BB), 256, SMEM_XC>>>(xn, kh, kl, x_feat, g_ln, b_ln, out);
}

// round 15
// speedup vs baseline: 1.1089x; 1.1089x over previous
#include <cuda_runtime.h>
#include <cuda_bf16.h>
#include <math.h>
#include <stdint.h>

#define BB   64
#define SS   1024
#define SZS  256
#define CC   256
#define NN   64
#define NKD  67
#define EPSV 1e-5f
#define PAD  257
#define PADK 260

// ------------------------- scratch (device globals) -------------------------
__device__ float g_xn [BB * SS * NN];       // x_n    [b][s][n]  16MB
__device__ float g_zc [BB * SZS * NN];      // z_core [b][s][n]   4MB
__device__ float g_kz [BB * CC * NN];       // kernels (z path)  [b][c][n]
__device__ float g_kxp[2 * BB * CC * NN];   // kernels_x partials [b][c][n]
__device__ __nv_bfloat16 g_kh[BB * CC * NN];  // kernels_x post-LN hi [b][c][n]
__device__ __nv_bfloat16 g_kl[BB * CC * NN];  // kernels_x post-LN lo [b][c][n]
__device__ float g_tem[BB * CC];

// ------------------------- helpers -------------------------
__device__ __forceinline__ uint32_t smem_u32(const void* p) {
    uint32_t a;
    asm("{ .reg .u64 tmp; cvta.to.shared.u64 tmp, %1; cvt.u32.u64 %0, tmp; }"
        : "=r"(a) : "l"(p));
    return a;
}
__device__ __forceinline__ void split_pack(float x0, float x1, uint32_t& h, uint32_t& l) {
    __nv_bfloat162 hp = __floats2bfloat162_rn(x0, x1);
    float r0 = x0 - __bfloat162float(hp.x);
    float r1 = x1 - __bfloat162float(hp.y);
    __nv_bfloat162 lp = __floats2bfloat162_rn(r0, r1);
    h = *reinterpret_cast<uint32_t*>(&hp);
    l = *reinterpret_cast<uint32_t*>(&lp);
}
__device__ __forceinline__ void ldm4(uint32_t addr, uint32_t* r) {
    asm volatile("ldmatrix.sync.aligned.m8n8.x4.shared.b16 {%0,%1,%2,%3}, [%4];"
                 : "=r"(r[0]), "=r"(r[1]), "=r"(r[2]), "=r"(r[3]) : "r"(addr));
}
__device__ __forceinline__ void mma16816(float* d, const uint32_t* a, const uint32_t* b) {
    asm volatile(
        "mma.sync.aligned.m16n8k16.row.col.f32.bf16.bf16.f32 "
        "{%0,%1,%2,%3}, {%4,%5,%6,%7}, {%8,%9}, {%0,%1,%2,%3};"
        : "+f"(d[0]), "+f"(d[1]), "+f"(d[2]), "+f"(d[3])
        : "r"(a[0]), "r"(a[1]), "r"(a[2]), "r"(a[3]), "r"(b[0]), "r"(b[1]));
}
__device__ __forceinline__ void cp16(uint32_t dst, const void* src) {
    asm volatile("cp.async.cg.shared.global [%0], [%1], 16;" :: "r"(dst), "l"(src));
}
__device__ __forceinline__ void cpcommit() {
    asm volatile("cp.async.commit_group;" ::: "memory");
}
template<int N> __device__ __forceinline__ void cpwait() {
    asm volatile("cp.async.wait_group %0;" :: "n"(N) : "memory");
}

// bf16 smem row stride (bytes): 72 halves = 144B
#define RS 144
// raw staging strides (floats)
#define RAWA_F  68
#define RAWAT_F 132
#define RAWB_F  68
// gemm smem layout (bytes) — single-buffered raw, 2 CTAs/SM
#define OFF_AH   0
#define OFF_AL   18432
#define OFF_BH   36864
#define OFF_BL   46080
#define OFF_RAWA 55296
#define OFF_RAWB 90112
#define OFF_BIAS 107520
#define SMEM_KG  107776

// ---------------------------------------------------------------------------
// chunk loader: gmem -> raw fp32 smem via cp.async (all coalesced)
// ---------------------------------------------------------------------------
template<bool TRA, bool TRB>
__device__ __forceinline__ void kg_load(const float* Ab, int lda, const float* Bb,
                                        int ldb, int m0, int k0, char* sm, int t) {
    uint32_t ra = smem_u32(sm + OFF_RAWA);
    uint32_t rb = smem_u32(sm + OFF_RAWB);
    if (!TRA) {
#pragma unroll
        for (int i = 0; i < 8; i++) {
            int u = t + i * 256;
            int r = u >> 4, kq = u & 15;
            cp16(ra + r * (RAWA_F * 4) + kq * 16,
                 Ab + (size_t)(m0 + r) * lda + k0 + kq * 4);
        }
    } else {
#pragma unroll
        for (int i = 0; i < 8; i++) {
            int u = t + i * 256;
            int r = u >> 5, mq = u & 31;
            cp16(ra + r * (RAWAT_F * 4) + mq * 16,
                 Ab + (size_t)(k0 + r) * lda + m0 + mq * 4);
        }
    }
    if (!TRB) {
#pragma unroll
        for (int i = 0; i < 4; i++) {
            int u = t + i * 256;
            int r = u >> 4, kq = u & 15;
            cp16(rb + r * (RAWB_F * 4) + kq * 16,
                 Bb + (size_t)r * ldb + k0 + kq * 4);
        }
    } else {
#pragma unroll
        for (int i = 0; i < 4; i++) {
            int u = t + i * 256;
            int r = u >> 4, nq = u & 15;
            cp16(rb + r * (RAWB_F * 4) + nq * 16,
                 Bb + (size_t)(k0 + r) * ldb + nq * 4);
        }
    }
}

// convert raw fp32 -> split-bf16 operand buffers (transpose happens here)
template<bool TRA, bool TRB>
__device__ __forceinline__ void kg_convert(char* sm, int t) {
    float* rawA = (float*)(sm + OFF_RAWA);
    float* rawB = (float*)(sm + OFF_RAWB);
    char* sAh = sm + OFF_AH; char* sAl = sm + OFF_AL;
    char* sBh = sm + OFF_BH; char* sBl = sm + OFF_BL;
    if (!TRA) {
#pragma unroll
        for (int i = 0; i < 8; i++) {
            int u = t + i * 256;
            int r = u >> 4, kq = u & 15;
            float4 v = *(const float4*)(rawA + r * RAWA_F + kq * 4);
            uint32_t h0, l0, h1, l1;
            split_pack(v.x, v.y, h0, l0);
            split_pack(v.z, v.w, h1, l1);
            *(uint2*)(sAh + r * RS + kq * 8) = make_uint2(h0, h1);
            *(uint2*)(sAl + r * RS + kq * 8) = make_uint2(l0, l1);
        }
    } else {
#pragma unroll
        for (int i = 0; i < 8; i++) {
            int u = t + i * 256;
            int m = u & 127, kg = u >> 7;
            float f0 = rawA[(kg * 4 + 0) * RAWAT_F + m];
            float f1 = rawA[(kg * 4 + 1) * RAWAT_F + m];
            float f2 = rawA[(kg * 4 + 2) * RAWAT_F + m];
            float f3 = rawA[(kg * 4 + 3) * RAWAT_F + m];
            uint32_t h0, l0, h1, l1;
            split_pack(f0, f1, h0, l0);
            split_pack(f2, f3, h1, l1);
            *(uint2*)(sAh + m * RS + kg * 8) = make_uint2(h0, h1);
            *(uint2*)(sAl + m * RS + kg * 8) = make_uint2(l0, l1);
        }
    }
    if (!TRB) {
#pragma unroll
        for (int i = 0; i < 4; i++) {
            int u = t + i * 256;
            int r = u >> 4, kq = u & 15;
            float4 v = *(const float4*)(rawB + r * RAWB_F + kq * 4);
            uint32_t h0, l0, h1, l1;
            split_pack(v.x, v.y, h0, l0);
            split_pack(v.z, v.w, h1, l1);
            *(uint2*)(sBh + r * RS + kq * 8) = make_uint2(h0, h1);
            *(uint2*)(sBl + r * RS + kq * 8) = make_uint2(l0, l1);
        }
    } else {
#pragma unroll
        for (int i = 0; i < 4; i++) {
            int u = t + i * 256;
            int n = u & 63, kg = u >> 6;
            float f0 = rawB[(kg * 4 + 0) * RAWB_F + n];
            float f1 = rawB[(kg * 4 + 1) * RAWB_F + n];
            float f2 = rawB[(kg * 4 + 2) * RAWB_F + n];
            float f3 = rawB[(kg * 4 + 3) * RAWB_F + n];
            uint32_t h0, l0, h1, l1;
            split_pack(f0, f1, h0, l0);
            split_pack(f2, f3, h1, l1);
            *(uint2*)(sBh + n * RS + kg * 8) = make_uint2(h0, h1);
            *(uint2*)(sBl + n * RS + kg * 8) = make_uint2(l0, l1);
        }
    }
}

// ---------------------------------------------------------------------------
// gemm_tile<TRA,TRB>: D[m0..m0+127, 0..63] += sum_k A*B (+bias).
// 256 threads = 8 warps (4M x 2N). Single-buffered; residency=2 gives overlap.
// ---------------------------------------------------------------------------
template<bool TRA, bool TRB>
__device__ void gemm_tile(const float* __restrict__ Ab, int lda,
                          const float* __restrict__ Bb, int ldb,
                          float* __restrict__ Db, int ldd,
                          int m0, int Ktot, const float* __restrict__ bias,
                          char* sm) {
    uint32_t sb = smem_u32(sm);
    int t = threadIdx.x, warp = t >> 5, l = t & 31;
    int wm = (warp & 3) * 32;
    int wn = (warp >> 2) * 32;
    float* sBias = (float*)(sm + OFF_BIAS);
    if (bias && t < 64) sBias[t] = bias[t];

    float acc[2][4][4];
#pragma unroll
    for (int i = 0; i < 2; i++)
#pragma unroll
        for (int j = 0; j < 4; j++)
#pragma unroll
            for (int q = 0; q < 4; q++) acc[i][j][q] = 0.f;

    uint32_t aRow = wm + (l & 15);
    uint32_t aOff = ((l >> 4) & 1) * 16;
    uint32_t aHi = sb + OFF_AH + aRow * RS + aOff;
    uint32_t aLo = sb + OFF_AL + aRow * RS + aOff;
    uint32_t bRow = wn + (l & 7) + ((l & 16) ? 8 : 0);
    uint32_t bOff = (l & 8) ? 16 : 0;
    uint32_t bHi = sb + OFF_BH + bRow * RS + bOff;
    uint32_t bLo = sb + OFF_BL + bRow * RS + bOff;

    int nch = Ktot >> 6;
    for (int ch = 0; ch < nch; ch++) {
        kg_load<TRA, TRB>(Ab, lda, Bb, ldb, m0, ch << 6, sm, t);
        cpcommit();
        cpwait<0>();
        __syncthreads();
        kg_convert<TRA, TRB>(sm, t);
        __syncthreads();
#pragma unroll
        for (int ks = 0; ks < 4; ks++) {
            uint32_t ah[2][4], al[2][4], bh[2][4], bl[2][4];
#pragma unroll
            for (int mf = 0; mf < 2; mf++) {
                ldm4(aHi + mf * (16 * RS) + ks * 32, ah[mf]);
                ldm4(aLo + mf * (16 * RS) + ks * 32, al[mf]);
            }
#pragma unroll
            for (int p = 0; p < 2; p++) {
                ldm4(bHi + p * (16 * RS) + ks * 32, bh[p]);
                ldm4(bLo + p * (16 * RS) + ks * 32, bl[p]);
            }
#pragma unroll
            for (int mf = 0; mf < 2; mf++)
#pragma unroll
                for (int nf = 0; nf < 4; nf++) {
                    const uint32_t* bhp = &bh[nf >> 1][(nf & 1) * 2];
                    const uint32_t* blp = &bl[nf >> 1][(nf & 1) * 2];
                    mma16816(acc[mf][nf], ah[mf], bhp);
                    mma16816(acc[mf][nf], ah[mf], blp);
                    mma16816(acc[mf][nf], al[mf], bhp);
                }
        }
        __syncthreads();
    }

#pragma unroll
    for (int mf = 0; mf < 2; mf++)
#pragma unroll
        for (int nf = 0; nf < 4; nf++) {
            int row = m0 + wm + mf * 16 + (l >> 2);
            int col = wn + nf * 8 + (l & 3) * 2;
            float b0 = bias ? sBias[col] : 0.f;
            float b1 = bias ? sBias[col + 1] : 0.f;
            *(float2*)(Db + (size_t)row * ldd + col) =
                make_float2(acc[mf][nf][0] + b0, acc[mf][nf][1] + b1);
            *(float2*)(Db + (size_t)(row + 8) * ldd + col) =
                make_float2(acc[mf][nf][2] + b0, acc[mf][nf][3] + b1);
        }
}

// ---------------------------------------------------------------------------
// merged launch 1: x_n = X@Wx+bx (512 tiles) and z_core = Z@Wz+bz (128 tiles)
// ---------------------------------------------------------------------------
__global__ void __launch_bounds__(256, 2) kLinAll(
    const float* __restrict__ xf, const float* __restrict__ Wx, const float* __restrict__ bx,
    const float* __restrict__ zf, const float* __restrict__ Wz, const float* __restrict__ bz,
    float* __restrict__ xn, float* __restrict__ zcp) {
    extern __shared__ char sm[];
    int bid = blockIdx.x;
    if (bid < 512) {
        int b = bid >> 3, m0 = (bid & 7) * 128;
        gemm_tile<false, true>(xf + (size_t)b * SS * CC, CC, Wx, NN,
                               xn + (size_t)b * SS * NN, NN, m0, CC, bx, sm);
    } else {
        int zi = bid - 512;
        int b = zi >> 1, m0 = (zi & 1) * 128;
        gemm_tile<false, true>(zf + (size_t)b * SZS * CC, CC, Wz, NN,
                               zcp + (size_t)b * SZS * NN, NN, m0, CC, bz, sm);
    }
}

// ---------------------------------------------------------------------------
// merged launch 2: kx partials (s-split x2, 256 tiles) and kz (128 tiles)
// ---------------------------------------------------------------------------
__global__ void __launch_bounds__(256, 2) kOuterAll(
    const float* __restrict__ xf, const float* __restrict__ zf,
    const float* __restrict__ xn, const float* __restrict__ zcp,
    float* __restrict__ kxp, float* __restrict__ kz) {
    extern __shared__ char sm[];
    int bid = blockIdx.x;
    if (bid < 256) {
        int b = bid >> 2, q = bid & 3, tile = q & 1, half = q >> 1;
        gemm_tile<true, true>(
            xf + (size_t)b * SS * CC + (size_t)half * 512 * CC, CC,
            xn + (size_t)b * SS * NN + (size_t)half * 512 * NN, NN,
            kxp + (size_t)half * BB * CC * NN + (size_t)b * CC * NN, NN,
            tile * 128, 512, nullptr, sm);
    } else {
        int zi = bid - 256;
        int b = zi >> 1, tile = zi & 1;
        gemm_tile<true, true>(
            zf + (size_t)b * SZS * CC, CC, zcp + (size_t)b * SZS * NN, NN,
            kz + (size_t)b * CC * NN, NN, tile * 128, SZS, nullptr, sm);
    }
}

// ---------------------------------------------------------------------------
// kD v2b: dysep conv atten + layernorm + proto + tem. grid(64), 512 threads.
// dy GEMM register-tiled 4m x 4jj; sKz stride PADK=260 (16B-aligned float4
// rows), sV stride PAD=257 (scalar access only), WdynT stride 260.
// smem floats: sKz 0(16640) sV 16640(16448) sW 33088(17680, reused as depth
// 64x256) sDy 50768(4352) sPr 55120(64). total 55184 fl = 220736 B.
// ---------------------------------------------------------------------------
#define DW 260
__global__ void kD(const float* __restrict__ Wdyn, const float* __restrict__ bdyn,
                   const float* __restrict__ gn, const float* __restrict__ bn,
                   const float* __restrict__ Wp, const float* __restrict__ bp) {
    extern __shared__ float smf[];
    float* sKz = smf;             // 64 x PADK (reused later as sP, stride CC)
    float* sV  = smf + 16640;     // 64 x PAD
    float* sW  = smf + 33088;     // WdynT [jj][c] stride DW; later depth 64x256
    float* sDy = smf + 50768;     // 64 x 68
    float* sPr = smf + 55120;     // 64
    int b = blockIdx.x, t = threadIdx.x;

    const float* kzb = g_kz + (size_t)b * CC * NN;
    const float* kx0 = g_kxp + (size_t)b * CC * NN;
    const float* kx1 = g_kxp + (size_t)BB * CC * NN + (size_t)b * CC * NN;
    for (int idx = t; idx < CC * NN; idx += 512) {
        int c = idx >> 6, n = idx & 63;
        sKz[n * PADK + c] = kzb[idx];
        sV [n * PAD  + c] = kx0[idx] + kx1[idx];
    }
    // stage Wdyn transposed: sW[jj*DW + c]; zero pad row 67
    for (int idx = t; idx < CC * NKD; idx += 512) {
        int c = idx / NKD, jj = idx - c * NKD;
        sW[jj * DW + c] = Wdyn[idx];
    }
    for (int idx = t; idx < CC; idx += 512) sW[67 * DW + idx] = 0.f;
    __syncthreads();

    // dy[m,jj] = kz[m,:] . WdynT[jj,:] + bdyn[jj]  — 4m x 4jj register tiles
    if (t < 272) {
        int mg = t / 17, jg = t - (t / 17) * 17;
        int m = mg * 4, jj = jg * 4;
        float acc[4][4];
#pragma unroll
        for (int i = 0; i < 4; i++)
#pragma unroll
            for (int j = 0; j < 4; j++) acc[i][j] = 0.f;
        const float* kzr = sKz + m * PADK;
        const float* wr  = sW + jj * DW;
#pragma unroll 4
        for (int c = 0; c < CC; c += 4) {
            float4 kv[4], wv[4];
#pragma unroll
            for (int i = 0; i < 4; i++) kv[i] = *(const float4*)(kzr + i * PADK + c);
#pragma unroll
            for (int j = 0; j < 4; j++) wv[j] = *(const float4*)(wr + j * DW + c);
#pragma unroll
            for (int i = 0; i < 4; i++)
#pragma unroll
                for (int j = 0; j < 4; j++) {
                    acc[i][j] += kv[i].x * wv[j].x + kv[i].y * wv[j].y
                               + kv[i].z * wv[j].z + kv[i].w * wv[j].w;
                }
        }
#pragma unroll
        for (int i = 0; i < 4; i++)
#pragma unroll
            for (int j = 0; j < 4; j++)
                if (jj + j < NKD)
                    sDy[(m + i) * 68 + jj + j] = bdyn[jj + j] + acc[i][j];
    }
    __syncthreads();

    // depth(m,c) = relu(w0*v[c-1] + w1*v[c] + w2*v[c+1])  (overwrites sW)
    float* sU = sW;
    for (int idx = t; idx < NN * CC; idx += 512) {
        int m = idx >> 8, c = idx & 255;
        float w0 = sDy[m * 68 + 0], w1 = sDy[m * 68 + 1], w2 = sDy[m * 68 + 2];
        float vm = (c > 0)   ? sV[m * PAD + c - 1] : 0.f;
        float v0 = sV[m * PAD + c];
        float vp = (c < 255) ? sV[m * PAD + c + 1] : 0.f;
        float d = w0 * vm + w1 * v0 + w2 * vp;
        sU[idx] = d > 0.f ? d : 0.f;
    }
    __syncthreads();

    // point(n,c) = sum_m wp[n,m]*depth[m,c]; layernorm over c
    int tx = t & 31, ty = t >> 5;
    float4 acc[4][2];
#pragma unroll
    for (int i = 0; i < 4; i++) {
        acc[i][0] = make_float4(0.f, 0.f, 0.f, 0.f);
        acc[i][1] = make_float4(0.f, 0.f, 0.f, 0.f);
    }
#pragma unroll 2
    for (int m = 0; m < NN; m++) {
        float4 d0 = *(const float4*)(sU + m * CC + tx * 4);
        float4 d1 = *(const float4*)(sU + m * CC + tx * 4 + 128);
#pragma unroll
        for (int i = 0; i < 4; i++) {
            float w = sDy[(ty * 4 + i) * 68 + 3 + m];
            acc[i][0].x += w * d0.x; acc[i][0].y += w * d0.y;
            acc[i][0].z += w * d0.z; acc[i][0].w += w * d0.w;
            acc[i][1].x += w * d1.x; acc[i][1].y += w * d1.y;
            acc[i][1].z += w * d1.z; acc[i][1].w += w * d1.w;
        }
    }
    __syncthreads();

    float* sP = sKz;   // stride CC, 16384 fl < 16640 region
    float4 gg0 = *(const float4*)(gn + tx * 4);
    float4 gg1 = *(const float4*)(gn + tx * 4 + 128);
    float4 bb0 = *(const float4*)(bn + tx * 4);
    float4 bb1 = *(const float4*)(bn + tx * 4 + 128);
#pragma unroll
    for (int i = 0; i < 4; i++) {
        int n = ty * 4 + i;
        float4 v0 = acc[i][0], v1 = acc[i][1];
        float sum = v0.x + v0.y + v0.z + v0.w + v1.x + v1.y + v1.z + v1.w;
        float sq  = v0.x * v0.x + v0.y * v0.y + v0.z * v0.z + v0.w * v0.w
                  + v1.x * v1.x + v1.y * v1.y + v1.z * v1.z + v1.w * v1.w;
#pragma unroll
        for (int off = 16; off >= 1; off >>= 1) {
            sum += __shfl_xor_sync(0xffffffffu, sum, off);
            sq  += __shfl_xor_sync(0xffffffffu, sq, off);
        }
        float mu = sum * (1.f / 256.f);
        float var = sq * (1.f / 256.f) - mu * mu;
        float rs = rsqrtf(var + EPSV);
        float4 o0, o1;
        o0.x = (v0.x - mu) * rs * gg0.x + bb0.x;
        o0.y = (v0.y - mu) * rs * gg0.y + bb0.y;
        o0.z = (v0.z - mu) * rs * gg0.z + bb0.z;
        o0.w = (v0.w - mu) * rs * gg0.w + bb0.w;
        o1.x = (v1.x - mu) * rs * gg1.x + bb1.x;
        o1.y = (v1.y - mu) * rs * gg1.y + bb1.y;
        o1.z = (v1.z - mu) * rs * gg1.z + bb1.z;
        o1.w = (v1.w - mu) * rs * gg1.w + bb1.w;
        *(float4*)(sP + n * CC + tx * 4) = o0;
        *(float4*)(sP + n * CC + tx * 4 + 128) = o1;
    }
    __syncthreads();

    // write split-bf16 kernels [c][n]
    __nv_bfloat16* kh = g_kh + (size_t)b * CC * NN;
    __nv_bfloat16* kl = g_kl + (size_t)b * CC * NN;
    for (int idx = t; idx < NN * CC; idx += 512) {
        int c = idx >> 6, n = idx & 63;
        float v = sP[n * CC + c];
        __nv_bfloat16 h = __float2bfloat16(v);
        float lo = v - __bfloat162float(h);
        kh[idx] = h;
        kl[idx] = __float2bfloat16(lo);
    }

    // proto[n] = ka[n,:] . Wp + bp
    if (t < NN) {
        float a0 = 0.f, a1 = 0.f, a2 = 0.f, a3 = 0.f;
        for (int c = 0; c < CC; c += 4) {
            float4 p = *(const float4*)(sP + t * CC + c);
            float4 w = *(const float4*)(Wp + c);
            a0 += p.x * w.x; a1 += p.y * w.y; a2 += p.z * w.z; a3 += p.w * w.w;
        }
        sPr[t] = bp[0] + ((a0 + a1) + (a2 + a3));
    }
    __syncthreads();

    // tem[c] = sigmoid(sum_n proto[n] * ka[n,c])
    if (t < CC) {
        float a0 = 0.f, a1 = 0.f, a2 = 0.f, a3 = 0.f;
        for (int n = 0; n < NN; n += 4) {
            a0 += sPr[n + 0] * sP[(n + 0) * CC + t];
            a1 += sPr[n + 1] * sP[(n + 1) * CC + t];
            a2 += sPr[n + 2] * sP[(n + 2) * CC + t];
            a3 += sPr[n + 3] * sP[(n + 3) * CC + t];
        }
        float s = (a0 + a1) + (a2 + a3);
        g_tem[b * CC + t] = 1.f / (1.f + expf(-s));
    }
}

// ---------------------------------------------------------------------------
// kXC v4 (unchanged, measured-good): B-persistent, grid(4,64), 2 CTAs/SM.
// ---------------------------------------------------------------------------
#define XC_AH   0
#define XC_AL   9216
#define XC_BH   18432
#define XC_BL   55296
#define XC_TEM  92160
#define XC_G    93184
#define XC_B2   94208
#define XC_SUM  95232
#define XC_SQ   96256
#define SMEM_XC 97280

__global__ void __launch_bounds__(256, 2) kXC(
    const float* __restrict__ xn, const __nv_bfloat16* __restrict__ kh,
    const __nv_bfloat16* __restrict__ kl, const float* __restrict__ xf,
    const float* __restrict__ gl, const float* __restrict__ bl,
    float* __restrict__ out)
{
    extern __shared__ char sm[];
    uint32_t sb = smem_u32(sm);
    float* sTem = (float*)(sm + XC_TEM);
    float* sG   = (float*)(sm + XC_G);
    float* sB2  = (float*)(sm + XC_B2);
    float* sSum = (float*)(sm + XC_SUM);
    float* sSq  = (float*)(sm + XC_SQ);

    int t = threadIdx.x, warp = t >> 5, l = t & 31;
    int b = blockIdx.y;
    int sbase = blockIdx.x * 256;
    int wm = (warp & 1) * 32;
    int wn = (warp >> 1) * 64;

    const __nv_bfloat16* Bh = kh + (size_t)b * CC * NN;
    const __nv_bfloat16* Bl = kl + (size_t)b * CC * NN;

#pragma unroll
    for (int i = 0; i < 8; i++) {
        int u = t + i * 256;
        int r = u >> 3, kq = u & 7;
        cp16(sb + XC_BH + r * RS + kq * 16, Bh + r * NN + kq * 8);
    }
#pragma unroll
    for (int i = 0; i < 8; i++) {
        int u = t + i * 256;
        int r = u >> 3, kq = u & 7;
        cp16(sb + XC_BL + r * RS + kq * 16, Bl + r * NN + kq * 8);
    }
    cpcommit();
    { sTem[t] = g_tem[b * CC + t]; sG[t] = gl[t]; sB2[t] = bl[t]; }
    cpwait<0>();
    __syncthreads();

    uint32_t aRow = wm + (l & 15);
    uint32_t aOff = ((l >> 4) & 1) * 16;
    uint32_t aHi = sb + XC_AH + aRow * RS + aOff;
    uint32_t aLo = sb + XC_AL + aRow * RS + aOff;
    uint32_t bRow = wn + (l & 7) + ((l & 16) ? 8 : 0);
    uint32_t bOff = (l & 8) ? 16 : 0;
    uint32_t bHi = sb + XC_BH + bRow * RS + bOff;
    uint32_t bLo = sb + XC_BL + bRow * RS + bOff;

    for (int it = 0; it < 4; it++) {
        int s0 = sbase + it * 64;
        const float* Ab = xn + ((size_t)b * SS + s0) * NN;

        if (it > 0) __syncthreads();

        {
            char* sAh = sm + XC_AH;
            char* sAl = sm + XC_AL;
            for (int idx = t; idx < 1024; idx += 256) {
                int r = idx >> 4, kq = idx & 15;
                float4 v = *(const float4*)(Ab + (size_t)r * NN + kq * 4);
                uint32_t h0, l0, h1, l1;
                split_pack(v.x, v.y, h0, l0);
                split_pack(v.z, v.w, h1, l1);
                *(uint2*)(sAh + r * RS + kq * 8) = make_uint2(h0, h1);
                *(uint2*)(sAl + r * RS + kq * 8) = make_uint2(l0, l1);
            }
        }
        __syncthreads();

        float acc[2][8][4];
#pragma unroll
        for (int i = 0; i < 2; i++)
#pragma unroll
            for (int j = 0; j < 8; j++)
#pragma unroll
                for (int q = 0; q < 4; q++) acc[i][j][q] = 0.f;

#pragma unroll
        for (int ks = 0; ks < 4; ks++) {
            uint32_t ah[2][4], al[2][4], bh[4][4], blr[4][4];
#pragma unroll
            for (int mf = 0; mf < 2; mf++) {
                ldm4(aHi + mf * (16 * RS) + ks * 32, ah[mf]);
                ldm4(aLo + mf * (16 * RS) + ks * 32, al[mf]);
            }
#pragma unroll
            for (int p = 0; p < 4; p++) {
                ldm4(bHi + p * (16 * RS) + ks * 32, bh[p]);
                ldm4(bLo + p * (16 * RS) + ks * 32, blr[p]);
            }
#pragma unroll
            for (int mf = 0; mf < 2; mf++)
#pragma unroll
                for (int nf = 0; nf < 8; nf++) {
                    const uint32_t* bhp = &bh[nf >> 1][(nf & 1) * 2];
                    const uint32_t* blp = &blr[nf >> 1][(nf & 1) * 2];
                    mma16816(acc[mf][nf], ah[mf], bhp);
                    mma16816(acc[mf][nf], ah[mf], blp);
                    mma16816(acc[mf][nf], al[mf], bhp);
                }
        }

        float psum[2][2], psq[2][2];
#pragma unroll
        for (int mf = 0; mf < 2; mf++)
#pragma unroll
            for (int h = 0; h < 2; h++) { psum[mf][h] = 0.f; psq[mf][h] = 0.f; }
#pragma unroll
        for (int nf = 0; nf < 8; nf++) {
            int col = wn + nf * 8 + (l & 3) * 2;
            float t0 = sTem[col], t1 = sTem[col + 1];
#pragma unroll
            for (int mf = 0; mf < 2; mf++) {
                acc[mf][nf][0] *= t0; acc[mf][nf][1] *= t1;
                acc[mf][nf][2] *= t0; acc[mf][nf][3] *= t1;
                psum[mf][0] += acc[mf][nf][0] + acc[mf][nf][1];
                psq [mf][0] += acc[mf][nf][0] * acc[mf][nf][0] + acc[mf][nf][1] * acc[mf][nf][1];
                psum[mf][1] += acc[mf][nf][2] + acc[mf][nf][3];
                psq [mf][1] += acc[mf][nf][2] * acc[mf][nf][2] + acc[mf][nf][3] * acc[mf][nf][3];
            }
        }
#pragma unroll
        for (int mf = 0; mf < 2; mf++)
#pragma unroll
            for (int h = 0; h < 2; h++) {
#pragma unroll
                for (int off = 1; off <= 2; off <<= 1) {
                    psum[mf][h] += __shfl_xor_sync(0xffffffffu, psum[mf][h], off);
                    psq [mf][h] += __shfl_xor_sync(0xffffffffu, psq [mf][h], off);
                }
                if ((l & 3) == 0) {
                    int r = wm + mf * 16 + h * 8 + (l >> 2);
                    sSum[r * 4 + (warp >> 1)] = psum[mf][h];
                    sSq [r * 4 + (warp >> 1)] = psq [mf][h];
                }
            }
        __syncthreads();

        const float* Xb = xf + ((size_t)b * SS + s0) * CC;
        float* Ob = out + ((size_t)b * SS + s0) * CC;
#pragma unroll
        for (int mf = 0; mf < 2; mf++)
#pragma unroll
            for (int h = 0; h < 2; h++) {
                int r = wm + mf * 16 + h * 8 + (l >> 2);
                float sum = sSum[r * 4] + sSum[r * 4 + 1] + sSum[r * 4 + 2] + sSum[r * 4 + 3];
                float sq  = sSq [r * 4] + sSq [r * 4 + 1] + sSq [r * 4 + 2] + sSq [r * 4 + 3];
                float mu = sum * (1.f / 256.f);
                float var = sq * (1.f / 256.f) - mu * mu;
                float rs = rsqrtf(var + EPSV);
#pragma unroll
                for (int nf = 0; nf < 8; nf++) {
                    int col = wn + nf * 8 + (l & 3) * 2;
                    float v0 = acc[mf][nf][h * 2], v1 = acc[mf][nf][h * 2 + 1];
                    float2 xv = *(const float2*)(Xb + (size_t)r * CC + col);
                    float o0 = fmaxf((v0 - mu) * rs * sG[col] + sB2[col], 0.f) + xv.x;
                    float o1 = fmaxf((v1 - mu) * rs * sG[col + 1] + sB2[col + 1], 0.f) + xv.y;
                    *(float2*)(Ob + (size_t)r * CC + col) = make_float2(o0, o1);
                }
            }
    }
}

// ---------------------------------------------------------------------------
extern "C" void kernel_launch(void* const* d_in, const int* in_sizes, int n_in,
                              void* d_out, int out_size) {
    const float* x_feat = (const float*)d_in[0];
    const float* z_feat = (const float*)d_in[1];
    const float* Wz     = (const float*)d_in[2];
    const float* bz     = (const float*)d_in[3];
    const float* Wx     = (const float*)d_in[4];
    const float* bx     = (const float*)d_in[5];
    const float* Wdyn   = (const float*)d_in[6];
    const float* bdyn   = (const float*)d_in[7];
    const float* gnorm  = (const float*)d_in[8];
    const float* bnorm  = (const float*)d_in[9];
    const float* Wp     = (const float*)d_in[10];
    const float* bp     = (const float*)d_in[11];
    const float* g_ln   = (const float*)d_in[12];
    const float* b_ln   = (const float*)d_in[13];
    float* out = (float*)d_out;

    float *xn, *zc, *kz, *kxp;
    __nv_bfloat16 *kh, *kl;
    cudaGetSymbolAddress((void**)&xn,  g_xn);
    cudaGetSymbolAddress((void**)&zc,  g_zc);
    cudaGetSymbolAddress((void**)&kz,  g_kz);
    cudaGetSymbolAddress((void**)&kxp, g_kxp);
    cudaGetSymbolAddress((void**)&kh,  g_kh);
    cudaGetSymbolAddress((void**)&kl,  g_kl);

    cudaFuncSetAttribute(kLinAll,   cudaFuncAttributeMaxDynamicSharedMemorySize, SMEM_KG);
    cudaFuncSetAttribute(kOuterAll, cudaFuncAttributeMaxDynamicSharedMemorySize, SMEM_KG);
    cudaFuncSetAttribute(kD,  cudaFuncAttributeMaxDynamicSharedMemorySize, 220736);
    cudaFuncSetAttribute(kXC, cudaFuncAttributeMaxDynamicSharedMemorySize, SMEM_XC);

    kLinAll<<<640, 256, SMEM_KG>>>(x_feat, Wx, bx, z_feat, Wz, bz, xn, zc);
    kOuterAll<<<384, 256, SMEM_KG>>>(x_feat, z_feat, xn, zc, kxp, kz);
    kD<<<BB, 512, 220736>>>(Wdyn, bdyn, gnorm, bnorm, Wp, bp);
    kXC<<<dim3(4, BB), 256, SMEM_XC>>>(xn, kh, kl, x_feat, g_ln, b_ln, out);
}